// round 1
// baseline (speedup 1.0000x reference)
#include <cuda_runtime.h>
#include <math.h>

#define NN   200000
#define MM   12
#define FF   64
#define NBR  41
#define NBRP 44
#define ORIG 92
#define BB   2000
#define SHH  9
#define NC   3
#define HF   128
#define NM   (NN*MM)
#define NPB  (NN/BB)   // 100 atoms per crystal
// folded: c0 * alpha * (1/M)
#define WSCALE (0.28209479177387814f * 0.125f / 12.0f)

// scratch (allocation-free rule: __device__ globals)
__device__ float g_x[(size_t)NN * FF];       // 51.2 MB
__device__ float g_y[(size_t)NN * FF];       // 51.2 MB
__device__ float g_w[(size_t)NC * NM];       // 28.8 MB

__device__ __forceinline__ float softplusf(float t) {
    // stable: max(t,0) + log1p(exp(-|t|))
    return fmaxf(t, 0.0f) + log1pf(__expf(-fabsf(t)));
}

// ---------------------------------------------------------------------------
// 1) x = atom_fea @ W_emb + b_emb      (200000 x 92) @ (92 x 64)
//    16 threads per atom, each computes 4 contiguous f.
// ---------------------------------------------------------------------------
__global__ __launch_bounds__(256) void embed_kernel(
    const float* __restrict__ af, const float* __restrict__ W,
    const float* __restrict__ b)
{
    __shared__ float sW[ORIG][FF];   // 23.5 KB
    __shared__ float sb[FF];
    for (int i = threadIdx.x; i < ORIG * FF; i += 256) sW[i >> 6][i & 63] = W[i];
    if (threadIdx.x < FF) sb[threadIdx.x] = b[threadIdx.x];
    __syncthreads();

    int a  = blockIdx.x * 16 + (threadIdx.x >> 4);
    int f0 = (threadIdx.x & 15) * 4;
    if (a >= NN) return;

    const float4* row4 = (const float4*)(af + (size_t)a * ORIG);  // 92*4B, 16B aligned
    float4 acc = make_float4(sb[f0], sb[f0 + 1], sb[f0 + 2], sb[f0 + 3]);
    #pragma unroll
    for (int k4 = 0; k4 < ORIG / 4; k4++) {
        float4 v = row4[k4];
        int k = k4 * 4;
        {
            float4 w = *(const float4*)&sW[k + 0][f0];
            acc.x += v.x * w.x; acc.y += v.x * w.y; acc.z += v.x * w.z; acc.w += v.x * w.w;
        }
        {
            float4 w = *(const float4*)&sW[k + 1][f0];
            acc.x += v.y * w.x; acc.y += v.y * w.y; acc.z += v.y * w.z; acc.w += v.y * w.w;
        }
        {
            float4 w = *(const float4*)&sW[k + 2][f0];
            acc.x += v.z * w.x; acc.y += v.z * w.y; acc.z += v.z * w.z; acc.w += v.z * w.w;
        }
        {
            float4 w = *(const float4*)&sW[k + 3][f0];
            acc.x += v.w * w.x; acc.y += v.w * w.y; acc.z += v.w * w.z; acc.w += v.w * w.w;
        }
    }
    *(float4*)&g_x[(size_t)a * FF + f0] = acc;
}

// ---------------------------------------------------------------------------
// 2) Per-edge radial scalar for all 3 conv layers in one pass over nbr_fea.
//    w[l][edge] = (softplus(e @ Wr1[l] + br1[l]) . Wr2[l][:,0] + br2[l][0]) * WSCALE
// ---------------------------------------------------------------------------
__global__ __launch_bounds__(128) void edge_kernel(
    const float* __restrict__ nbr_fea,
    const float* __restrict__ Wr1, const float* __restrict__ br1,
    const float* __restrict__ Wr2, const float* __restrict__ br2)
{
    __shared__ float sW1[NC][NBR][NBRP];   // 21.6 KB, rows padded to 44 floats
    __shared__ float sb1[NC][NBR];
    __shared__ float sw2[NC][NBR];
    __shared__ float sb2[NC];

    for (int idx = threadIdx.x; idx < NC * NBR * NBR; idx += 128) {
        int l = idx / (NBR * NBR);
        int r = idx - l * NBR * NBR;
        sW1[l][r / NBR][r % NBR] = Wr1[idx];
    }
    for (int idx = threadIdx.x; idx < NC * NBR; idx += 128) {
        sb1[idx / NBR][idx % NBR] = br1[idx];
        sw2[idx / NBR][idx % NBR] = Wr2[(size_t)idx * SHH];  // column 0 of Wr2[l]
    }
    if (threadIdx.x < NC) sb2[threadIdx.x] = br2[threadIdx.x * SHH];
    __syncthreads();

    int edge = blockIdx.x * 128 + threadIdx.x;
    if (edge >= NM) return;
    const float* e = nbr_fea + (size_t)edge * NBR;

    #pragma unroll 1
    for (int l = 0; l < NC; l++) {
        float acc[NBR];
        #pragma unroll
        for (int j = 0; j < NBR; j++) acc[j] = sb1[l][j];

        #pragma unroll 1
        for (int k = 0; k < NBR; k++) {
            float ek = __ldg(&e[k]);   // L1 hit on layers 1,2
            #pragma unroll
            for (int j = 0; j < NBR; j++) acc[j] += ek * sW1[l][k][j];
        }

        float w = sb2[l];
        #pragma unroll
        for (int j = 0; j < NBR; j++) w += softplusf(acc[j]) * sw2[l][j];

        g_w[(size_t)l * NM + edge] = w * WSCALE;
    }
}

// ---------------------------------------------------------------------------
// 3a) y[i] = sum_j w[l][i*M+j] * x[src_ij]     (weighted neighbor gather-sum)
//     16 threads (float4 each) per atom.
// ---------------------------------------------------------------------------
__global__ __launch_bounds__(256) void gather_kernel(
    const int* __restrict__ nbr_idx, int l)
{
    int gid = blockIdx.x * 256 + threadIdx.x;
    if (gid >= NN * 16) return;
    int i  = gid >> 4;
    int f4 = gid & 15;
    const float4* x4 = (const float4*)g_x;
    const float*  wl = g_w + (size_t)l * NM;

    float4 acc = make_float4(0.f, 0.f, 0.f, 0.f);
    #pragma unroll
    for (int j = 0; j < MM; j++) {
        int   s  = __ldg(&nbr_idx[i * MM + j]);
        float wj = __ldg(&wl[i * MM + j]);
        float4 v = x4[(size_t)s * 16 + f4];
        acc.x += wj * v.x; acc.y += wj * v.y; acc.z += wj * v.z; acc.w += wj * v.w;
    }
    ((float4*)g_y)[gid] = acc;
}

// ---------------------------------------------------------------------------
// 3b) x = y @ Wtp[l]        (200000 x 64) @ (64 x 64)
//     8 threads per atom, each computes 8 contiguous f.
// ---------------------------------------------------------------------------
__global__ __launch_bounds__(256) void tpgemm_kernel(const float* __restrict__ Wtp_l)
{
    __shared__ float sW[FF][FF];   // 16 KB
    for (int i = threadIdx.x; i < FF * FF; i += 256) sW[i >> 6][i & 63] = Wtp_l[i];
    __syncthreads();

    int a  = blockIdx.x * 32 + (threadIdx.x >> 3);
    int f0 = (threadIdx.x & 7) * 8;
    if (a >= NN) return;

    const float4* yrow = (const float4*)(g_y + (size_t)a * FF);
    float acc[8] = {0.f, 0.f, 0.f, 0.f, 0.f, 0.f, 0.f, 0.f};

    #pragma unroll
    for (int k4 = 0; k4 < FF / 4; k4++) {
        float4 v = yrow[k4];
        int k = k4 * 4;
        #pragma unroll
        for (int c = 0; c < 4; c++) {
            float vc = (c == 0) ? v.x : (c == 1) ? v.y : (c == 2) ? v.z : v.w;
            float4 w0 = *(const float4*)&sW[k + c][f0];
            float4 w1 = *(const float4*)&sW[k + c][f0 + 4];
            acc[0] += vc * w0.x; acc[1] += vc * w0.y; acc[2] += vc * w0.z; acc[3] += vc * w0.w;
            acc[4] += vc * w1.x; acc[5] += vc * w1.y; acc[6] += vc * w1.z; acc[7] += vc * w1.w;
        }
    }
    float* xo = g_x + (size_t)a * FF + f0;
    *(float4*)(xo)     = make_float4(acc[0], acc[1], acc[2], acc[3]);
    *(float4*)(xo + 4) = make_float4(acc[4], acc[5], acc[6], acc[7]);
}

// ---------------------------------------------------------------------------
// 4) crystal pooling + fc + out. One block (128 thr) per crystal.
// ---------------------------------------------------------------------------
__global__ __launch_bounds__(128) void pool_kernel(
    const int* __restrict__ cidx,
    const float* __restrict__ Wfc, const float* __restrict__ bfc,
    const float* __restrict__ Wout, const float* __restrict__ bout,
    float* __restrict__ out, float* __restrict__ hout)
{
    __shared__ float scrys[FF];
    __shared__ float sred[HF];
    int b    = blockIdx.x;
    int tid  = threadIdx.x;
    int f    = tid & 63;
    int half = tid >> 6;

    float acc = 0.f;
    for (int a = half * (NPB / 2); a < (half + 1) * (NPB / 2); a++) {
        int atom = __ldg(&cidx[b * NPB + a]);
        acc += g_x[(size_t)atom * FF + f];
    }
    if (half == 1) scrys[f] = acc;
    __syncthreads();
    if (half == 0) scrys[f] = (scrys[f] + acc) * (1.0f / NPB);
    __syncthreads();

    float hv = bfc[tid];
    #pragma unroll
    for (int k = 0; k < FF; k++) hv += scrys[k] * Wfc[k * HF + tid];
    hv = softplusf(hv);
    if (hout) hout[(size_t)b * HF + tid] = hv;

    sred[tid] = hv * Wout[tid];
    __syncthreads();
    #pragma unroll
    for (int s = 64; s > 0; s >>= 1) {
        if (tid < s) sred[tid] += sred[tid + s];
        __syncthreads();
    }
    if (tid == 0) out[b] = sred[0] + bout[0];
}

// ---------------------------------------------------------------------------
extern "C" void kernel_launch(void* const* d_in, const int* in_sizes, int n_in,
                              void* d_out, int out_size)
{
    const float* atom_fea = (const float*)d_in[0];
    const float* nbr_fea  = (const float*)d_in[1];
    const int*   nbr_idx  = (const int*)  d_in[2];
    const int*   cidx     = (const int*)  d_in[3];
    // d_in[4] = pos : unused (Y0 is a constant)
    const float* W_emb = (const float*)d_in[5];
    const float* b_emb = (const float*)d_in[6];
    const float* Wr1   = (const float*)d_in[7];
    const float* br1   = (const float*)d_in[8];
    const float* Wr2   = (const float*)d_in[9];
    const float* br2   = (const float*)d_in[10];
    const float* Wtp   = (const float*)d_in[11];
    const float* W_fc  = (const float*)d_in[12];
    const float* b_fc  = (const float*)d_in[13];
    const float* W_out = (const float*)d_in[14];
    const float* b_out = (const float*)d_in[15];

    float* out_f = (float*)d_out;
    float* h_f   = (out_size >= BB + BB * HF) ? out_f + BB : nullptr;

    embed_kernel<<<(NN + 15) / 16, 256>>>(atom_fea, W_emb, b_emb);
    edge_kernel<<<(NM + 127) / 128, 128>>>(nbr_fea, Wr1, br1, Wr2, br2);

    for (int l = 0; l < NC; l++) {
        gather_kernel<<<(NN * 16 + 255) / 256, 256>>>(nbr_idx, l);
        tpgemm_kernel<<<(NN + 31) / 32, 256>>>(Wtp + (size_t)l * FF * FF);
    }

    pool_kernel<<<BB, 128>>>(cidx, W_fc, b_fc, W_out, b_out, out_f, h_f);
}

// round 2
// speedup vs baseline: 1.2832x; 1.2832x over previous
#include <cuda_runtime.h>
#include <math.h>

#define NN   200000
#define MM   12
#define FF   64
#define NBR  41
#define NPAIR 21          // ceil(41/2) packed f32x2 pairs
#define ORIG 92
#define BB   2000
#define SHH  9
#define NC   3
#define HF   128
#define NM   (NN*MM)
#define NPB  (NN/BB)      // 100 atoms per crystal
#define APB  128          // atoms per conv block
// folded: c0 * alpha * (1/M)
#define WSCALE (0.28209479177387814f * 0.125f / 12.0f)

typedef unsigned long long ull;

// scratch (allocation-free rule: __device__ globals)
__device__ float g_x[(size_t)NN * FF];       // 51.2 MB
__device__ float g_y[(size_t)NN * FF];       // 51.2 MB
__device__ float g_w[(size_t)NC * NM];       // 28.8 MB

__device__ __forceinline__ float softplusf(float t) {
    return fmaxf(t, 0.0f) + log1pf(__expf(-fabsf(t)));
}

// ---- packed fp32x2 helpers (SASS FFMA2; ptxas won't emit these itself) ----
__device__ __forceinline__ ull pack2(float lo, float hi) {
    ull r; asm("mov.b64 %0, {%1, %2};" : "=l"(r) : "f"(lo), "f"(hi)); return r;
}
__device__ __forceinline__ void unpack2(ull v, float& lo, float& hi) {
    asm("mov.b64 {%0, %1}, %2;" : "=f"(lo), "=f"(hi) : "l"(v));
}
__device__ __forceinline__ ull fma2(ull a, ull b, ull c) {
    ull d; asm("fma.rn.f32x2 %0, %1, %2, %3;" : "=l"(d) : "l"(a), "l"(b), "l"(c));
    return d;
}

// ---------------------------------------------------------------------------
// 1) x = atom_fea @ W_emb + b_emb      (200000 x 92) @ (92 x 64)
// ---------------------------------------------------------------------------
__global__ __launch_bounds__(256) void embed_kernel(
    const float* __restrict__ af, const float* __restrict__ W,
    const float* __restrict__ b)
{
    __shared__ float sW[ORIG][FF];
    __shared__ float sb[FF];
    for (int i = threadIdx.x; i < ORIG * FF; i += 256) sW[i >> 6][i & 63] = W[i];
    if (threadIdx.x < FF) sb[threadIdx.x] = b[threadIdx.x];
    __syncthreads();

    int a  = blockIdx.x * 16 + (threadIdx.x >> 4);
    int f0 = (threadIdx.x & 15) * 4;
    if (a >= NN) return;

    const float4* row4 = (const float4*)(af + (size_t)a * ORIG);
    ull acc0 = pack2(sb[f0], sb[f0 + 1]);
    ull acc1 = pack2(sb[f0 + 2], sb[f0 + 3]);
    #pragma unroll
    for (int k4 = 0; k4 < ORIG / 4; k4++) {
        float4 v = row4[k4];
        int k = k4 * 4;
        #pragma unroll
        for (int c = 0; c < 4; c++) {
            float vc = (c == 0) ? v.x : (c == 1) ? v.y : (c == 2) ? v.z : v.w;
            ull v2 = pack2(vc, vc);
            const ull* wr = (const ull*)&sW[k + c][f0];
            acc0 = fma2(v2, wr[0], acc0);
            acc1 = fma2(v2, wr[1], acc1);
        }
    }
    float4 o;
    unpack2(acc0, o.x, o.y);
    unpack2(acc1, o.z, o.w);
    *(float4*)&g_x[(size_t)a * FF + f0] = o;
}

// ---------------------------------------------------------------------------
// 2) Per-edge radial scalar, all 3 layers, packed f32x2 inner product.
//    w[l][edge] = (softplus(e @ Wr1[l] + br1[l]) . Wr2[l][:,0] + br2[l][0]) * WSCALE
// ---------------------------------------------------------------------------
__global__ __launch_bounds__(128) void edge_kernel(
    const float* __restrict__ nbr_fea,
    const float* __restrict__ Wr1, const float* __restrict__ br1,
    const float* __restrict__ Wr2, const float* __restrict__ br2)
{
    __shared__ ull   sW1p[NC][NBR][NPAIR];  // weight pairs (j,j+1), pad hi=0 at j=40
    __shared__ ull   sb1p[NC][NPAIR];
    __shared__ float sw2[NC][2 * NPAIR];    // col 0 of Wr2, padded with 0
    __shared__ float sb2[NC];

    for (int idx = threadIdx.x; idx < NC * NBR * NPAIR; idx += 128) {
        int l = idx / (NBR * NPAIR);
        int r = idx - l * NBR * NPAIR;
        int k = r / NPAIR, j = r % NPAIR;
        float lo = Wr1[((size_t)l * NBR + k) * NBR + 2 * j];
        float hi = (2 * j + 1 < NBR) ? Wr1[((size_t)l * NBR + k) * NBR + 2 * j + 1] : 0.f;
        sW1p[l][k][j] = pack2(lo, hi);
    }
    for (int idx = threadIdx.x; idx < NC * NPAIR; idx += 128) {
        int l = idx / NPAIR, j = idx % NPAIR;
        float lo = br1[l * NBR + 2 * j];
        float hi = (2 * j + 1 < NBR) ? br1[l * NBR + 2 * j + 1] : 0.f;
        sb1p[l][j] = pack2(lo, hi);
    }
    for (int idx = threadIdx.x; idx < NC * 2 * NPAIR; idx += 128) {
        int l = idx / (2 * NPAIR), j = idx % (2 * NPAIR);
        sw2[l][j] = (j < NBR) ? Wr2[((size_t)l * NBR + j) * SHH] : 0.f;
    }
    if (threadIdx.x < NC) sb2[threadIdx.x] = br2[threadIdx.x * SHH];
    __syncthreads();

    int edge = blockIdx.x * 128 + threadIdx.x;
    if (edge >= NM) return;
    const float* e = nbr_fea + (size_t)edge * NBR;

    float ereg[NBR];
    #pragma unroll
    for (int k = 0; k < NBR; k++) ereg[k] = __ldg(&e[k]);

    #pragma unroll 1
    for (int l = 0; l < NC; l++) {
        ull acc[NPAIR];
        #pragma unroll
        for (int j = 0; j < NPAIR; j++) acc[j] = sb1p[l][j];

        #pragma unroll 1
        for (int k = 0; k < NBR; k++) {
            ull ek2 = pack2(ereg[k], ereg[k]);
            #pragma unroll
            for (int j = 0; j < NPAIR; j++) acc[j] = fma2(ek2, sW1p[l][k][j], acc[j]);
        }

        float w = sb2[l];
        #pragma unroll
        for (int j = 0; j < NPAIR; j++) {
            float lo, hi; unpack2(acc[j], lo, hi);
            w += softplusf(lo) * sw2[l][2 * j] + softplusf(hi) * sw2[l][2 * j + 1];
        }
        g_w[(size_t)l * NM + edge] = w * WSCALE;
    }
}

// ---------------------------------------------------------------------------
// 3) Fused conv layer: y = weighted gather of xin, xout = y @ Wtp[l]
//    Block: 128 atoms. Phase 1 gathers into smem (rows padded to 68),
//    phase 2 register-tiles 4 atoms x 8 outputs per thread with f32x2.
// ---------------------------------------------------------------------------
__global__ __launch_bounds__(256) void conv_kernel(
    const int* __restrict__ nbr_idx, const float* __restrict__ Wtp_l,
    const float* __restrict__ wl,
    const float* __restrict__ xin, float* __restrict__ xout)
{
    __shared__ float y_s[APB][68];   // 34.8 KB (pad 68 -> conflict-free column reads)
    __shared__ float sW[FF][FF];     // 16 KB

    int t = threadIdx.x;
    for (int i = t; i < FF * FF; i += 256) sW[i >> 6][i & 63] = Wtp_l[i];

    int base = blockIdx.x * APB;
    int fg = t & 7;
    int f0 = fg * 8;

    // ---- phase 1: weighted neighbor gather into y_s ----
    #pragma unroll 1
    for (int r = 0; r < 4; r++) {
        int la = (t >> 3) + r * 32;
        int a  = base + la;
        float4 a0 = make_float4(0.f, 0.f, 0.f, 0.f);
        float4 a1 = make_float4(0.f, 0.f, 0.f, 0.f);
        if (a < NN) {
            #pragma unroll
            for (int j = 0; j < MM; j++) {
                int   s  = __ldg(&nbr_idx[a * MM + j]);
                float wj = __ldg(&wl[a * MM + j]);
                const float4* xr = (const float4*)(xin + (size_t)s * FF + f0);
                float4 v0 = __ldg(&xr[0]);
                float4 v1 = __ldg(&xr[1]);
                a0.x += wj * v0.x; a0.y += wj * v0.y; a0.z += wj * v0.z; a0.w += wj * v0.w;
                a1.x += wj * v1.x; a1.y += wj * v1.y; a1.z += wj * v1.z; a1.w += wj * v1.w;
            }
        }
        *(float4*)&y_s[la][f0]     = a0;
        *(float4*)&y_s[la][f0 + 4] = a1;
    }
    __syncthreads();

    // ---- phase 2: GEMM, thread = 4 atoms x 8 outputs (4 f32x2 pairs) ----
    int la0 = (t >> 3) * 4;
    ull acc[4][4];
    #pragma unroll
    for (int i = 0; i < 4; i++)
        #pragma unroll
        for (int p = 0; p < 4; p++) acc[i][p] = 0ULL;

    #pragma unroll 4
    for (int k4 = 0; k4 < FF / 4; k4++) {
        float4 yv[4];
        #pragma unroll
        for (int i = 0; i < 4; i++) yv[i] = *(const float4*)&y_s[la0 + i][k4 * 4];
        #pragma unroll
        for (int c = 0; c < 4; c++) {
            int k = k4 * 4 + c;
            ulonglong2 wa = *(const ulonglong2*)&sW[k][f0];      // pairs 0,1
            ulonglong2 wb = *(const ulonglong2*)&sW[k][f0 + 4];  // pairs 2,3
            #pragma unroll
            for (int i = 0; i < 4; i++) {
                float yc = (c == 0) ? yv[i].x : (c == 1) ? yv[i].y : (c == 2) ? yv[i].z : yv[i].w;
                ull y2 = pack2(yc, yc);
                acc[i][0] = fma2(y2, wa.x, acc[i][0]);
                acc[i][1] = fma2(y2, wa.y, acc[i][1]);
                acc[i][2] = fma2(y2, wb.x, acc[i][2]);
                acc[i][3] = fma2(y2, wb.y, acc[i][3]);
            }
        }
    }

    #pragma unroll
    for (int i = 0; i < 4; i++) {
        int a = base + la0 + i;
        if (a >= NN) break;
        float4 o0, o1;
        unpack2(acc[i][0], o0.x, o0.y);
        unpack2(acc[i][1], o0.z, o0.w);
        unpack2(acc[i][2], o1.x, o1.y);
        unpack2(acc[i][3], o1.z, o1.w);
        float* xo = xout + (size_t)a * FF + f0;
        *(float4*)(xo)     = o0;
        *(float4*)(xo + 4) = o1;
    }
}

// ---------------------------------------------------------------------------
// 4) crystal pooling + fc + out. One block (128 thr) per crystal.
// ---------------------------------------------------------------------------
__global__ __launch_bounds__(128) void pool_kernel(
    const float* __restrict__ xin,
    const int* __restrict__ cidx,
    const float* __restrict__ Wfc, const float* __restrict__ bfc,
    const float* __restrict__ Wout, const float* __restrict__ bout,
    float* __restrict__ out, float* __restrict__ hout)
{
    __shared__ float scrys[FF];
    __shared__ float sred[HF];
    int b    = blockIdx.x;
    int tid  = threadIdx.x;
    int f    = tid & 63;
    int half = tid >> 6;

    float acc = 0.f;
    for (int a = half * (NPB / 2); a < (half + 1) * (NPB / 2); a++) {
        int atom = __ldg(&cidx[b * NPB + a]);
        acc += xin[(size_t)atom * FF + f];
    }
    if (half == 1) scrys[f] = acc;
    __syncthreads();
    if (half == 0) scrys[f] = (scrys[f] + acc) * (1.0f / NPB);
    __syncthreads();

    float hv = bfc[tid];
    #pragma unroll
    for (int k = 0; k < FF; k++) hv += scrys[k] * Wfc[k * HF + tid];
    hv = softplusf(hv);
    if (hout) hout[(size_t)b * HF + tid] = hv;

    sred[tid] = hv * Wout[tid];
    __syncthreads();
    #pragma unroll
    for (int s = 64; s > 0; s >>= 1) {
        if (tid < s) sred[tid] += sred[tid + s];
        __syncthreads();
    }
    if (tid == 0) out[b] = sred[0] + bout[0];
}

// ---------------------------------------------------------------------------
extern "C" void kernel_launch(void* const* d_in, const int* in_sizes, int n_in,
                              void* d_out, int out_size)
{
    const float* atom_fea = (const float*)d_in[0];
    const float* nbr_fea  = (const float*)d_in[1];
    const int*   nbr_idx  = (const int*)  d_in[2];
    const int*   cidx     = (const int*)  d_in[3];
    // d_in[4] = pos : unused (Y0 is a constant)
    const float* W_emb = (const float*)d_in[5];
    const float* b_emb = (const float*)d_in[6];
    const float* Wr1   = (const float*)d_in[7];
    const float* br1   = (const float*)d_in[8];
    const float* Wr2   = (const float*)d_in[9];
    const float* br2   = (const float*)d_in[10];
    const float* Wtp   = (const float*)d_in[11];
    const float* W_fc  = (const float*)d_in[12];
    const float* b_fc  = (const float*)d_in[13];
    const float* W_out = (const float*)d_in[14];
    const float* b_out = (const float*)d_in[15];

    float* out_f = (float*)d_out;
    float* h_f   = (out_size >= BB + BB * HF) ? out_f + BB : nullptr;

    float* gx; cudaGetSymbolAddress((void**)&gx, g_x);
    float* gy; cudaGetSymbolAddress((void**)&gy, g_y);
    float* gw; cudaGetSymbolAddress((void**)&gw, g_w);

    embed_kernel<<<(NN + 15) / 16, 256>>>(atom_fea, W_emb, b_emb);
    edge_kernel<<<(NM + 127) / 128, 128>>>(nbr_fea, Wr1, br1, Wr2, br2);

    // layer ping-pong: x -> y -> x -> y
    conv_kernel<<<(NN + APB - 1) / APB, 256>>>(nbr_idx, Wtp + 0 * FF * FF, gw + 0 * (size_t)NM, gx, gy);
    conv_kernel<<<(NN + APB - 1) / APB, 256>>>(nbr_idx, Wtp + 1 * FF * FF, gw + 1 * (size_t)NM, gy, gx);
    conv_kernel<<<(NN + APB - 1) / APB, 256>>>(nbr_idx, Wtp + 2 * FF * FF, gw + 2 * (size_t)NM, gx, gy);

    pool_kernel<<<BB, 128>>>(gy, cidx, W_fc, b_fc, W_out, b_out, out_f, h_f);
}